// round 9
// baseline (speedup 1.0000x reference)
#include <cuda_runtime.h>
#include <cuda_fp16.h>
#include <cstdint>

#define THREADS 512
#define DDIM    128
#define NNBR    32
#define GB      4                 // batches per group -> 128 GEMM rows
#define LRELU   0.2f

#define PITCH_B 272               // bytes/row of fp16 tiles (17*16B -> ldsm conflict-free)

// ---------------- SMEM layout (bytes) ----------------
#define SM_W      0                          // w^T fp16, 128 x 272B = 34816
#define SM_NB0    34816                      // nb fp16 buffer 0 (34816)
#define SM_NB1    69632                      // nb fp16 buffer 1 (34816)
#define SM_SELF   104448                     // self [2 buf][4][128] fp32 = 4096
#define SM_Q      108544                     // 128 fp32 = 512
#define SM_PART   109056                     // score partials [4 g][4 nw][32] fp32 = 2048
#define SM_TOTAL  111104                     // ~108.5 KB

__device__ __forceinline__ uint32_t smem_u32(const void* p) {
    uint32_t a;
    asm("{ .reg .u64 t; cvta.to.shared.u64 t, %1; cvt.u32.u64 %0, t; }" : "=r"(a) : "l"(p));
    return a;
}
__device__ __forceinline__ void ldsm_x4(uint32_t* r, uint32_t addr) {
    asm volatile("ldmatrix.sync.aligned.m8n8.x4.shared.b16 {%0,%1,%2,%3}, [%4];"
                 : "=r"(r[0]), "=r"(r[1]), "=r"(r[2]), "=r"(r[3]) : "r"(addr));
}
__device__ __forceinline__ void mma16816(float* d, const uint32_t* a, const uint32_t* b) {
    asm volatile("mma.sync.aligned.m16n8k16.row.col.f32.f16.f16.f32 "
                 "{%0,%1,%2,%3}, {%4,%5,%6,%7}, {%8,%9}, {%0,%1,%2,%3};"
                 : "+f"(d[0]), "+f"(d[1]), "+f"(d[2]), "+f"(d[3])
                 : "r"(a[0]), "r"(a[1]), "r"(a[2]), "r"(a[3]), "r"(b[0]), "r"(b[1]));
}
#define QBAR(g) asm volatile("bar.sync %0, 128;" :: "r"((g) + 1) : "memory")

// convert a float4 (4 consecutive k-values) to 2 packed fp16x2 words
__device__ __forceinline__ uint2 pack_f16x4(float4 v) {
    __half h0 = __float2half_rn(v.x), h1 = __float2half_rn(v.y);
    __half h2 = __float2half_rn(v.z), h3 = __float2half_rn(v.w);
    uint2 hv;
    hv.x = ((uint32_t)__half_as_ushort(h1) << 16) | __half_as_ushort(h0);
    hv.y = ((uint32_t)__half_as_ushort(h3) << 16) | __half_as_ushort(h2);
    return hv;
}

__global__ void __launch_bounds__(THREADS, 1)
hete_agg_hmma6(const float* __restrict__ self_v,
               const float* __restrict__ nb_g,
               const float* __restrict__ w_g,
               const float* __restrict__ q_g,
               float* __restrict__ out,
               int B) {
    extern __shared__ char smem[];
    const uint32_t smb = smem_u32(smem);
    const int tid  = threadIdx.x;
    const int lane = tid & 31;
    const int wid  = tid >> 5;              // 0..15
    const int g    = wid >> 2;              // batch within group (rows g*32..+31)
    const int nw   = wid & 3;               // e-slice
    const int mbase = g * 32;
    const int nbase = nw * 32;

    float* self_s = reinterpret_cast<float*>(smem + SM_SELF);
    float* q_s    = reinterpret_cast<float*>(smem + SM_Q);
    float* part_s = reinterpret_cast<float*>(smem + SM_PART);

    // ---- stage w^T fp16 (once); q ----
    for (int idx = tid; idx < DDIM * DDIM; idx += THREADS) {
        int k = idx >> 7, e = idx & 127;
        *reinterpret_cast<__half*>(smem + SM_W + e * PITCH_B + k * 2) =
            __float2half_rn(w_g[idx]);
    }
    if (tid < DDIM) q_s[tid] = q_g[tid];

    const int ngroups = (B + GB - 1) / GB;

    // ---- prologue: stage nb + self for first group (buf 0) ----
    int grp = blockIdx.x;
    if (grp < ngroups) {
        const int b0 = grp * GB;
        #pragma unroll
        for (int it = 0; it < 8; it++) {
            int unit = it * THREADS + tid;      // float4 index in 128x32
            int row = unit >> 5;
            int b = b0 + (row >> 5);
            int bc = (b < B) ? b : (B - 1);
            float4 v = *reinterpret_cast<const float4*>(
                nb_g + ((size_t)bc * NNBR + (row & 31)) * DDIM + (unit & 31) * 4);
            *reinterpret_cast<uint2*>(smem + SM_NB0
                + (uint32_t)row * PITCH_B + (uint32_t)(unit & 31) * 8) = pack_f16x4(v);
        }
        {
            int b = b0 + (tid >> 7);
            int bc = (b < B) ? b : (B - 1);
            self_s[tid] = self_v[(size_t)bc * DDIM + (tid & 127)];
        }
    }
    __syncthreads();            // w + first nb staged

    // ---- hoist w fragments for this warp's 32-col slice: resident all groups ----
    // B pair-load: lanes 0-7 rows n0-7/k0-7; 8-15 n0-7/k8-15; 16-23 n8-15/k0-7; 24-31 n8-15/k8-15
    uint32_t Bf[8][2][4];       // [ks][pair p -> n-tiles 2p,2p+1][4 regs]
    {
        const uint32_t b_ptr = smb + SM_W
            + (uint32_t)(nbase + ((lane >> 4) << 3) + (lane & 7)) * PITCH_B
            + (((lane >> 3) & 1) << 4);
        #pragma unroll
        for (int ks = 0; ks < 8; ks++)
            #pragma unroll
            for (int p = 0; p < 2; p++)
                ldsm_x4(Bf[ks][p], b_ptr + p * 16 * PITCH_B + ks * 32);
    }

    int buf = 0;
    bool first = true;
    for (; grp < ngroups; grp += gridDim.x) {
        const int b0 = grp * GB;
        if (!first) __syncthreads();    // staged nb[buf]/self[buf] visible
        first = false;

        // ========== GEMM: acc = nb_f16 @ w_f16^T (A from smem, B from regs) ==========
        float acc[2][4][4];
        #pragma unroll
        for (int mt = 0; mt < 2; mt++)
            #pragma unroll
            for (int nt = 0; nt < 4; nt++)
                #pragma unroll
                for (int j = 0; j < 4; j++) acc[mt][nt][j] = 0.f;

        const uint32_t a_ptr = smb + (buf ? SM_NB1 : SM_NB0)
            + (uint32_t)(mbase + (lane & 15)) * PITCH_B + ((lane >> 4) << 4);

        #pragma unroll
        for (int ks = 0; ks < 8; ks++) {
            const uint32_t ka = ks * 32;
            uint32_t Ar[2][4];
            ldsm_x4(Ar[0], a_ptr + ka);
            ldsm_x4(Ar[1], a_ptr + 16 * PITCH_B + ka);
            #pragma unroll
            for (int p = 0; p < 2; p++)
                #pragma unroll
                for (int hf = 0; hf < 2; hf++)
                    #pragma unroll
                    for (int mt = 0; mt < 2; mt++)
                        mma16816(acc[mt][2 * p + hf], Ar[mt], &Bf[ks][p][2 * hf]);
        }

        // ---- prefetch next group's nb (convert to packed fp16 on arrival) + self ----
        const int ngrp = grp + gridDim.x;
        const bool hasnext = (ngrp < ngroups);
        uint2 praw[8];
        float selfraw;
        if (hasnext) {
            const int b0n = ngrp * GB;
            #pragma unroll
            for (int it = 0; it < 8; it++) {
                int unit = it * THREADS + tid;
                int row = unit >> 5;
                int b = b0n + (row >> 5);
                int bc = (b < B) ? b : (B - 1);
                float4 v = *reinterpret_cast<const float4*>(
                    nb_g + ((size_t)bc * NNBR + (row & 31)) * DDIM + (unit & 31) * 4);
                praw[it] = pack_f16x4(v);
            }
            {
                int b = b0n + (tid >> 7);
                int bc = (b < B) ? b : (B - 1);
                selfraw = self_v[(size_t)bc * DDIM + (tid & 127)];
            }
        }

        // ========== register-resident epilogue ==========
        // thread owns: rows n = mt*16 + 8h + (lane>>2); cols e = nbase + nt*8 + 2(lane&3)+cc
        {
            const float* selfb = self_s + buf * (GB * DDIM) + g * DDIM;

            // per-thread score partials for 4 rows (mt,h) over its 8 e's
            float s[2][2] = {{0.f, 0.f}, {0.f, 0.f}};
            #pragma unroll
            for (int nt = 0; nt < 4; nt++)
                #pragma unroll
                for (int cc = 0; cc < 2; cc++) {
                    const int e = nbase + nt * 8 + 2 * (lane & 3) + cc;
                    const float sve = selfb[e];
                    const float qve = q_s[e];
                    #pragma unroll
                    for (int mt = 0; mt < 2; mt++)
                        #pragma unroll
                        for (int h = 0; h < 2; h++) {
                            float x = sve * acc[mt][nt][2 * h + cc];
                            x = (x >= 0.f) ? x : LRELU * x;
                            s[mt][h] = fmaf(x, qve, s[mt][h]);
                        }
                }
            // reduce across lanes sharing a row (lane&3 varies): xor 1, 2
            #pragma unroll
            for (int mt = 0; mt < 2; mt++)
                #pragma unroll
                for (int h = 0; h < 2; h++) {
                    s[mt][h] += __shfl_xor_sync(0xffffffffu, s[mt][h], 1);
                    s[mt][h] += __shfl_xor_sync(0xffffffffu, s[mt][h], 2);
                }
            if ((lane & 3) == 0) {
                float* pp = part_s + (g * 4 + nw) * 32;
                #pragma unroll
                for (int mt = 0; mt < 2; mt++)
                    #pragma unroll
                    for (int h = 0; h < 2; h++)
                        pp[mt * 16 + 8 * h + (lane >> 2)] = s[mt][h];
            }
            QBAR(g);

            // full score (lane = n), softmax over 32 neighbors
            const float* pg = part_s + g * 4 * 32;
            float sc = pg[lane] + pg[32 + lane] + pg[64 + lane] + pg[96 + lane];
            float mx = sc;
            #pragma unroll
            for (int o = 16; o; o >>= 1) mx = fmaxf(mx, __shfl_xor_sync(0xffffffffu, mx, o));
            float ex = expf(sc - mx);
            float ssum = ex;
            #pragma unroll
            for (int o = 16; o; o >>= 1) ssum += __shfl_xor_sync(0xffffffffu, ssum, o);
            const float alpha = ex / ssum;

            // weighted sum: pe[nt][cc] = sum_{mt,h} alpha_row * acc
            float ar[2][2];
            #pragma unroll
            for (int mt = 0; mt < 2; mt++)
                #pragma unroll
                for (int h = 0; h < 2; h++)
                    ar[mt][h] = __shfl_sync(0xffffffffu, alpha, mt * 16 + 8 * h + (lane >> 2));
            float pe[4][2];
            #pragma unroll
            for (int nt = 0; nt < 4; nt++)
                #pragma unroll
                for (int cc = 0; cc < 2; cc++) {
                    float v = 0.f;
                    #pragma unroll
                    for (int mt = 0; mt < 2; mt++)
                        #pragma unroll
                        for (int h = 0; h < 2; h++)
                            v = fmaf(ar[mt][h], acc[mt][nt][2 * h + cc], v);
                    pe[nt][cc] = v;
                }
            // reduce across lanes sharing cols (lane>>2 varies): xor 4, 8, 16
            #pragma unroll
            for (int nt = 0; nt < 4; nt++)
                #pragma unroll
                for (int cc = 0; cc < 2; cc++) {
                    #pragma unroll
                    for (int o = 4; o <= 16; o <<= 1)
                        pe[nt][cc] += __shfl_xor_sync(0xffffffffu, pe[nt][cc], o);
                }
            // lanes 0..3 write final out for e = nbase + nt*8 + 2*lane + cc
            const int b = b0 + g;
            if (lane < 4 && b < B) {
                float* ob = out + (size_t)b * DDIM + nbase + 2 * lane;
                #pragma unroll
                for (int nt = 0; nt < 4; nt++)
                    *reinterpret_cast<float2*>(ob + nt * 8) = make_float2(pe[nt][0], pe[nt][1]);
            }
        }

        // ---- commit prefetched nb/self into the other buffer ----
        if (hasnext) {
            const uint32_t nb_next = buf ? SM_NB0 : SM_NB1;
            #pragma unroll
            for (int it = 0; it < 8; it++) {
                int unit = it * THREADS + tid;
                *reinterpret_cast<uint2*>(smem + nb_next
                    + (uint32_t)(unit >> 5) * PITCH_B + (uint32_t)(unit & 31) * 8) = praw[it];
            }
            self_s[(buf ^ 1) * (GB * DDIM) + tid] = selfraw;
        }
        buf ^= 1;
    }
}

extern "C" void kernel_launch(void* const* d_in, const int* in_sizes, int n_in,
                              void* d_out, int out_size) {
    const float* self_v = (const float*)d_in[0];   // [B, 128]
    const float* nb_g   = (const float*)d_in[1];   // [B, 32, 128]
    const float* w_g    = (const float*)d_in[2];   // [128, 128]
    const float* q_g    = (const float*)d_in[3];   // [128, 1]
    float* out = (float*)d_out;

    const int B = in_sizes[0] / DDIM;
    const int ngroups = (B + GB - 1) / GB;

    cudaFuncSetAttribute(hete_agg_hmma6, cudaFuncAttributeMaxDynamicSharedMemorySize, SM_TOTAL);

    int dev = 0, nsm = 148;
    cudaGetDevice(&dev);
    cudaDeviceGetAttribute(&nsm, cudaDevAttrMultiProcessorCount, dev);
    int grid = (ngroups < nsm) ? ngroups : nsm;

    hete_agg_hmma6<<<grid, THREADS, SM_TOTAL>>>(self_v, nb_g, w_g, q_g, out, B);
}

// round 10
// speedup vs baseline: 1.2909x; 1.2909x over previous
#include <cuda_runtime.h>
#include <cuda_fp16.h>
#include <cstdint>

#define THREADS 512
#define DDIM    128
#define NNBR    32
#define GB      4                 // batches per group (one per quarter)
#define LRELU   0.2f

#define PITCH_B 272               // bytes/row of fp16 tiles (17*16B -> ldsm conflict-free)

// ---------------- SMEM layout (bytes) ----------------
#define SM_W      0                          // w^T fp16, 128 x 272B = 34816
#define SM_NB0    34816                      // nb fp16 buffer 0 (34816)
#define SM_NB1    69632                      // nb fp16 buffer 1 (34816)
#define SM_SELF   104448                     // self [2 buf][4][128] fp32 = 4096
#define SM_Q      108544                     // 128 fp32 = 512
#define SM_PART   109056                     // score partials [4 g][4 nw][32] fp32 = 2048
#define SM_TOTAL  111104                     // ~108.5 KB

__device__ __forceinline__ uint32_t smem_u32(const void* p) {
    uint32_t a;
    asm("{ .reg .u64 t; cvta.to.shared.u64 t, %1; cvt.u32.u64 %0, t; }" : "=r"(a) : "l"(p));
    return a;
}
__device__ __forceinline__ void ldsm_x4(uint32_t* r, uint32_t addr) {
    asm volatile("ldmatrix.sync.aligned.m8n8.x4.shared.b16 {%0,%1,%2,%3}, [%4];"
                 : "=r"(r[0]), "=r"(r[1]), "=r"(r[2]), "=r"(r[3]) : "r"(addr));
}
__device__ __forceinline__ void mma16816(float* d, const uint32_t* a, const uint32_t* b) {
    asm volatile("mma.sync.aligned.m16n8k16.row.col.f32.f16.f16.f32 "
                 "{%0,%1,%2,%3}, {%4,%5,%6,%7}, {%8,%9}, {%0,%1,%2,%3};"
                 : "+f"(d[0]), "+f"(d[1]), "+f"(d[2]), "+f"(d[3])
                 : "r"(a[0]), "r"(a[1]), "r"(a[2]), "r"(a[3]), "r"(b[0]), "r"(b[1]));
}
#define QBAR(g) asm volatile("bar.sync %0, 128;" :: "r"((g) + 1) : "memory")

// pack float4 -> 2x fp16x2 via cvt.rn.f16x2.f32 (2 instructions)
__device__ __forceinline__ uint2 pack_f16x4(float4 v) {
    uint2 r;
    asm("cvt.rn.f16x2.f32 %0, %1, %2;" : "=r"(r.x) : "f"(v.y), "f"(v.x));
    asm("cvt.rn.f16x2.f32 %0, %1, %2;" : "=r"(r.y) : "f"(v.w), "f"(v.z));
    return r;
}

__global__ void __launch_bounds__(THREADS, 1)
hete_agg_hmma7(const float* __restrict__ self_v,
               const float* __restrict__ nb_g,
               const float* __restrict__ w_g,
               const float* __restrict__ q_g,
               float* __restrict__ out,
               int B) {
    extern __shared__ char smem[];
    const uint32_t smb = smem_u32(smem);
    const int tid  = threadIdx.x;
    const int lane = tid & 31;
    const int wid  = tid >> 5;              // 0..15
    const int g    = wid >> 2;              // quarter / batch-in-group
    const int nw   = wid & 3;               // e-slice
    const int htid = tid & 127;             // thread within quarter
    const int mrow0 = g * 32;               // this quarter's nb rows
    const int nbase = nw * 32;

    float* self_s = reinterpret_cast<float*>(smem + SM_SELF);
    float* q_s    = reinterpret_cast<float*>(smem + SM_Q);
    float* part_s = reinterpret_cast<float*>(smem + SM_PART);

    // ---- stage w^T fp16 (once); q ----
    for (int idx = tid; idx < DDIM * DDIM; idx += THREADS) {
        int k = idx >> 7, e = idx & 127;
        *reinterpret_cast<__half*>(smem + SM_W + e * PITCH_B + k * 2) =
            __float2half_rn(w_g[idx]);
    }
    if (tid < DDIM) q_s[tid] = q_g[tid];

    const int ngroups = (B + GB - 1) / GB;

    // ---- prologue: each quarter stages its own batch (buf 0) ----
    int grp = blockIdx.x;
    if (grp < ngroups) {
        const int b = grp * GB + g;
        const int bc = (b < B) ? b : (B - 1);
        #pragma unroll
        for (int it = 0; it < 8; it++) {
            int unit = it * 128 + htid;        // float4 index within 32x32
            int rl = unit >> 5;                // local row 0..31
            float4 v = *reinterpret_cast<const float4*>(
                nb_g + ((size_t)bc * NNBR + rl) * DDIM + (unit & 31) * 4);
            *reinterpret_cast<uint2*>(smem + SM_NB0
                + (uint32_t)(mrow0 + rl) * PITCH_B + (uint32_t)(unit & 31) * 8) = pack_f16x4(v);
        }
        self_s[g * DDIM + htid] = self_v[(size_t)bc * DDIM + htid];
    }
    __syncthreads();    // w + all quarters' first nb visible (one-time, CTA-wide)

    int buf = 0;
    for (; grp < ngroups; grp += gridDim.x) {
        const int b = grp * GB + g;

        // ========== GEMM: acc = nb_f16[g] @ w_f16^T ==========
        float acc[2][4][4];
        #pragma unroll
        for (int mt = 0; mt < 2; mt++)
            #pragma unroll
            for (int nt = 0; nt < 4; nt++)
                #pragma unroll
                for (int j = 0; j < 4; j++) acc[mt][nt][j] = 0.f;

        const uint32_t a_ptr = smb + (buf ? SM_NB1 : SM_NB0)
            + (uint32_t)(mrow0 + (lane & 15)) * PITCH_B + ((lane >> 4) << 4);
        // B pair-load: lanes 0-7 rows n0-7/k0-7; 8-15 n0-7/k8-15; 16-23 n8-15/k0-7; 24-31 n8-15/k8-15
        const uint32_t b_ptr = smb + SM_W
            + (uint32_t)(nbase + ((lane >> 4) << 3) + (lane & 7)) * PITCH_B
            + (((lane >> 3) & 1) << 4);

        #pragma unroll
        for (int ks = 0; ks < 8; ks++) {
            const uint32_t ka = ks * 32;
            uint32_t Ar[2][4], Bp[2][4];
            ldsm_x4(Ar[0], a_ptr + ka);
            ldsm_x4(Ar[1], a_ptr + 16 * PITCH_B + ka);
            ldsm_x4(Bp[0], b_ptr + ka);
            ldsm_x4(Bp[1], b_ptr + 16 * PITCH_B + ka);
            #pragma unroll
            for (int p = 0; p < 2; p++)
                #pragma unroll
                for (int hf = 0; hf < 2; hf++)
                    #pragma unroll
                    for (int mt = 0; mt < 2; mt++)
                        mma16816(acc[mt][2 * p + hf], Ar[mt], &Bp[p][2 * hf]);
        }

        // ---- prefetch this quarter's next batch (LDG latency overlaps epilogue) ----
        const int ngrp = grp + gridDim.x;
        const bool hasnext = (ngrp < ngroups);
        uint2 praw[8];
        float selfraw;
        if (hasnext) {
            const int bn = ngrp * GB + g;
            const int bc = (bn < B) ? bn : (B - 1);
            #pragma unroll
            for (int it = 0; it < 8; it++) {
                int unit = it * 128 + htid;
                int rl = unit >> 5;
                float4 v = *reinterpret_cast<const float4*>(
                    nb_g + ((size_t)bc * NNBR + rl) * DDIM + (unit & 31) * 4);
                praw[it] = pack_f16x4(v);
            }
            selfraw = self_v[(size_t)bc * DDIM + htid];
        }

        // ========== register-resident epilogue (quarter-local) ==========
        // thread owns: rows n = mt*16 + 8h + (lane>>2); cols e = nbase + nt*8 + 2(lane&3)+cc
        {
            const float* selfb = self_s + buf * (GB * DDIM) + g * DDIM;

            float s[2][2] = {{0.f, 0.f}, {0.f, 0.f}};
            #pragma unroll
            for (int nt = 0; nt < 4; nt++)
                #pragma unroll
                for (int cc = 0; cc < 2; cc++) {
                    const int e = nbase + nt * 8 + 2 * (lane & 3) + cc;
                    const float sve = selfb[e];
                    const float qve = q_s[e];
                    #pragma unroll
                    for (int mt = 0; mt < 2; mt++)
                        #pragma unroll
                        for (int h = 0; h < 2; h++) {
                            float x = sve * acc[mt][nt][2 * h + cc];
                            x = (x >= 0.f) ? x : LRELU * x;
                            s[mt][h] = fmaf(x, qve, s[mt][h]);
                        }
                }
            #pragma unroll
            for (int mt = 0; mt < 2; mt++)
                #pragma unroll
                for (int h = 0; h < 2; h++) {
                    s[mt][h] += __shfl_xor_sync(0xffffffffu, s[mt][h], 1);
                    s[mt][h] += __shfl_xor_sync(0xffffffffu, s[mt][h], 2);
                }
            if ((lane & 3) == 0) {
                float* pp = part_s + (g * 4 + nw) * 32;
                #pragma unroll
                for (int mt = 0; mt < 2; mt++)
                    #pragma unroll
                    for (int h = 0; h < 2; h++)
                        pp[mt * 16 + 8 * h + (lane >> 2)] = s[mt][h];
            }
            QBAR(g);

            // full score (lane = n), softmax over 32 neighbors
            const float* pg = part_s + g * 4 * 32;
            float sc = pg[lane] + pg[32 + lane] + pg[64 + lane] + pg[96 + lane];
            float mx = sc;
            #pragma unroll
            for (int o = 16; o; o >>= 1) mx = fmaxf(mx, __shfl_xor_sync(0xffffffffu, mx, o));
            float ex = expf(sc - mx);
            float ssum = ex;
            #pragma unroll
            for (int o = 16; o; o >>= 1) ssum += __shfl_xor_sync(0xffffffffu, ssum, o);
            const float alpha = ex / ssum;

            float ar[2][2];
            #pragma unroll
            for (int mt = 0; mt < 2; mt++)
                #pragma unroll
                for (int h = 0; h < 2; h++)
                    ar[mt][h] = __shfl_sync(0xffffffffu, alpha, mt * 16 + 8 * h + (lane >> 2));
            float pe[4][2];
            #pragma unroll
            for (int nt = 0; nt < 4; nt++)
                #pragma unroll
                for (int cc = 0; cc < 2; cc++) {
                    float v = 0.f;
                    #pragma unroll
                    for (int mt = 0; mt < 2; mt++)
                        #pragma unroll
                        for (int h = 0; h < 2; h++)
                            v = fmaf(ar[mt][h], acc[mt][nt][2 * h + cc], v);
                    pe[nt][cc] = v;
                }
            #pragma unroll
            for (int nt = 0; nt < 4; nt++)
                #pragma unroll
                for (int cc = 0; cc < 2; cc++) {
                    #pragma unroll
                    for (int o = 4; o <= 16; o <<= 1)
                        pe[nt][cc] += __shfl_xor_sync(0xffffffffu, pe[nt][cc], o);
                }
            if (lane < 4 && b < B) {
                float* ob = out + (size_t)b * DDIM + nbase + 2 * lane;
                #pragma unroll
                for (int nt = 0; nt < 4; nt++)
                    *reinterpret_cast<float2*>(ob + nt * 8) = make_float2(pe[nt][0], pe[nt][1]);
            }
        }

        // ---- commit prefetched nb/self into the other buffer (quarter-local) ----
        if (hasnext) {
            const uint32_t nb_next = buf ? SM_NB0 : SM_NB1;
            #pragma unroll
            for (int it = 0; it < 8; it++) {
                int unit = it * 128 + htid;
                *reinterpret_cast<uint2*>(smem + nb_next
                    + (uint32_t)(mrow0 + (unit >> 5)) * PITCH_B
                    + (uint32_t)(unit & 31) * 8) = praw[it];
            }
            self_s[(buf ^ 1) * (GB * DDIM) + g * DDIM + htid] = selfraw;
        }
        QBAR(g);   // quarter-local: commit visible + part_s WAR protection
        buf ^= 1;
    }
}

extern "C" void kernel_launch(void* const* d_in, const int* in_sizes, int n_in,
                              void* d_out, int out_size) {
    const float* self_v = (const float*)d_in[0];   // [B, 128]
    const float* nb_g   = (const float*)d_in[1];   // [B, 32, 128]
    const float* w_g    = (const float*)d_in[2];   // [128, 128]
    const float* q_g    = (const float*)d_in[3];   // [128, 1]
    float* out = (float*)d_out;

    const int B = in_sizes[0] / DDIM;
    const int ngroups = (B + GB - 1) / GB;

    cudaFuncSetAttribute(hete_agg_hmma7, cudaFuncAttributeMaxDynamicSharedMemorySize, SM_TOTAL);

    int dev = 0, nsm = 148;
    cudaGetDevice(&dev);
    cudaDeviceGetAttribute(&nsm, cudaDevAttrMultiProcessorCount, dev);
    int grid = (ngroups < nsm) ? ngroups : nsm;

    hete_agg_hmma7<<<grid, THREADS, SM_TOTAL>>>(self_v, nb_g, w_g, q_g, out, B);
}

// round 11
// speedup vs baseline: 1.3178x; 1.0209x over previous
#include <cuda_runtime.h>
#include <cuda_fp16.h>
#include <cstdint>

#define THREADS 512
#define DDIM    128
#define NNBR    32
#define GB      8                 // batches per group (one per warp-pair)
#define LRELU   0.2f

#define PITCH_B 272               // bytes/row of fp16 tiles (17*16B -> ldsm conflict-free)

// ---------------- SMEM layout (bytes) ----------------
#define SM_W      0                          // w^T fp16, 128 x 272B = 34816
#define SM_NB0    34816                      // nb fp16 buffer 0: 256 rows x 272B = 69632
#define SM_NB1    104448                     // nb fp16 buffer 1
#define SM_SELF   174080                     // self [2 buf][8][128] fp32 = 8192
#define SM_Q      182272                     // 128 fp32 = 512
#define SM_PART   182784                     // score partials [8 g][2 nw][32] fp32 = 2048
#define SM_TOTAL  184832                     // ~180.5 KB

__device__ __forceinline__ uint32_t smem_u32(const void* p) {
    uint32_t a;
    asm("{ .reg .u64 t; cvta.to.shared.u64 t, %1; cvt.u32.u64 %0, t; }" : "=r"(a) : "l"(p));
    return a;
}
__device__ __forceinline__ void ldsm_x4(uint32_t* r, uint32_t addr) {
    asm volatile("ldmatrix.sync.aligned.m8n8.x4.shared.b16 {%0,%1,%2,%3}, [%4];"
                 : "=r"(r[0]), "=r"(r[1]), "=r"(r[2]), "=r"(r[3]) : "r"(addr));
}
__device__ __forceinline__ void mma16816(float* d, const uint32_t* a, const uint32_t* b) {
    asm volatile("mma.sync.aligned.m16n8k16.row.col.f32.f16.f16.f32 "
                 "{%0,%1,%2,%3}, {%4,%5,%6,%7}, {%8,%9}, {%0,%1,%2,%3};"
                 : "+f"(d[0]), "+f"(d[1]), "+f"(d[2]), "+f"(d[3])
                 : "r"(a[0]), "r"(a[1]), "r"(a[2]), "r"(a[3]), "r"(b[0]), "r"(b[1]));
}
#define PBAR(g) asm volatile("bar.sync %0, 64;" :: "r"((g) + 1) : "memory")

// pack float4 -> 2x fp16x2 via cvt.rn.f16x2.f32
__device__ __forceinline__ uint2 pack_f16x4(float4 v) {
    uint2 r;
    asm("cvt.rn.f16x2.f32 %0, %1, %2;" : "=r"(r.x) : "f"(v.y), "f"(v.x));
    asm("cvt.rn.f16x2.f32 %0, %1, %2;" : "=r"(r.y) : "f"(v.w), "f"(v.z));
    return r;
}

__global__ void __launch_bounds__(THREADS, 1)
hete_agg_hmma8(const float* __restrict__ self_v,
               const float* __restrict__ nb_g,
               const float* __restrict__ w_g,
               const float* __restrict__ q_g,
               float* __restrict__ out,
               int B) {
    extern __shared__ char smem[];
    const uint32_t smb = smem_u32(smem);
    const int tid  = threadIdx.x;
    const int lane = tid & 31;
    const int wid  = tid >> 5;              // 0..15
    const int g    = wid >> 1;              // batch-in-group 0..7 (warp pair)
    const int nw   = wid & 1;               // e-half
    const int ptid = tid & 63;              // thread within pair
    const int mrow0 = g * 32;               // this pair's nb rows
    const int nbase = nw * 64;

    float* self_s = reinterpret_cast<float*>(smem + SM_SELF);
    float* q_s    = reinterpret_cast<float*>(smem + SM_Q);
    float* part_s = reinterpret_cast<float*>(smem + SM_PART);

    // ---- stage w^T fp16 (once); q ----
    for (int idx = tid; idx < DDIM * DDIM; idx += THREADS) {
        int k = idx >> 7, e = idx & 127;
        *reinterpret_cast<__half*>(smem + SM_W + e * PITCH_B + k * 2) =
            __float2half_rn(w_g[idx]);
    }
    if (tid < DDIM) q_s[tid] = q_g[tid];

    const int ngroups = (B + GB - 1) / GB;

    // ---- prologue: stage first group's nb (256 rows) + self (buf 0) ----
    int grp = blockIdx.x;
    if (grp < ngroups) {
        const int b0 = grp * GB;
        #pragma unroll
        for (int it = 0; it < 16; it++) {
            int unit = it * THREADS + tid;      // float4 index in 256x32
            int row = unit >> 5;
            int b = b0 + (row >> 5);
            int bc = (b < B) ? b : (B - 1);
            float4 v = *reinterpret_cast<const float4*>(
                nb_g + ((size_t)bc * NNBR + (row & 31)) * DDIM + (unit & 31) * 4);
            *reinterpret_cast<uint2*>(smem + SM_NB0
                + (uint32_t)row * PITCH_B + (uint32_t)(unit & 31) * 8) = pack_f16x4(v);
        }
        #pragma unroll
        for (int j = 0; j < 2; j++) {
            int u = j * THREADS + tid;          // 0..1023 -> self [8][128]
            int b = b0 + (u >> 7);
            int bc = (b < B) ? b : (B - 1);
            self_s[u] = self_v[(size_t)bc * DDIM + (u & 127)];
        }
    }
    __syncthreads();    // one-time CTA-wide: w + first nb visible

    int buf = 0;
    for (; grp < ngroups; grp += gridDim.x) {
        const int b = grp * GB + g;
        const int ngrp = grp + gridDim.x;
        const bool hasnext = (ngrp < ngroups);
        const int b0n = ngrp * GB;
        const uint32_t nb_next = buf ? SM_NB0 : SM_NB1;

        // ---- prefetch pass 0 (rows 0..127 of next group) BEFORE GEMM ----
        uint2 praw[8];
        if (hasnext) {
            #pragma unroll
            for (int it = 0; it < 8; it++) {
                int unit = it * THREADS + tid;     // rows 0..127
                int row = unit >> 5;
                int bn = b0n + (row >> 5);
                int bc = (bn < B) ? bn : (B - 1);
                float4 v = *reinterpret_cast<const float4*>(
                    nb_g + ((size_t)bc * NNBR + (row & 31)) * DDIM + (unit & 31) * 4);
                praw[it] = pack_f16x4(v);
            }
        }

        // ========== GEMM: acc = nb_f16[g] @ w_f16^T (32 rows x 64 cols) ==========
        float acc[2][8][4];
        #pragma unroll
        for (int mt = 0; mt < 2; mt++)
            #pragma unroll
            for (int nt = 0; nt < 8; nt++)
                #pragma unroll
                for (int j = 0; j < 4; j++) acc[mt][nt][j] = 0.f;

        const uint32_t a_ptr = smb + (buf ? SM_NB1 : SM_NB0)
            + (uint32_t)(mrow0 + (lane & 15)) * PITCH_B + ((lane >> 4) << 4);
        // B pair-load: lanes 0-7 rows n0-7/k0-7; 8-15 n0-7/k8-15; 16-23 n8-15/k0-7; 24-31 n8-15/k8-15
        const uint32_t b_ptr = smb + SM_W
            + (uint32_t)(nbase + ((lane >> 4) << 3) + (lane & 7)) * PITCH_B
            + (((lane >> 3) & 1) << 4);

        #pragma unroll
        for (int ks = 0; ks < 8; ks++) {
            const uint32_t ka = ks * 32;
            uint32_t Ar[2][4];
            ldsm_x4(Ar[0], a_ptr + ka);
            ldsm_x4(Ar[1], a_ptr + 16 * PITCH_B + ka);
            #pragma unroll
            for (int p = 0; p < 4; p++) {          // pair p covers n-tiles 2p,2p+1
                uint32_t Bp[4];
                ldsm_x4(Bp, b_ptr + p * 16 * PITCH_B + ka);
                #pragma unroll
                for (int hf = 0; hf < 2; hf++)
                    #pragma unroll
                    for (int mt = 0; mt < 2; mt++)
                        mma16816(acc[mt][2 * p + hf], Ar[mt], &Bp[2 * hf]);
            }
        }

        // ---- commit pass 0 (data long ready), then issue prefetch pass 1 ----
        if (hasnext) {
            #pragma unroll
            for (int it = 0; it < 8; it++) {
                int unit = it * THREADS + tid;
                *reinterpret_cast<uint2*>(smem + nb_next
                    + (uint32_t)(unit >> 5) * PITCH_B + (uint32_t)(unit & 31) * 8) = praw[it];
            }
            #pragma unroll
            for (int it = 0; it < 8; it++) {       // rows 128..255
                int unit = 4096 + it * THREADS + tid;
                int row = unit >> 5;
                int bn = b0n + (row >> 5);
                int bc = (bn < B) ? bn : (B - 1);
                float4 v = *reinterpret_cast<const float4*>(
                    nb_g + ((size_t)bc * NNBR + (row & 31)) * DDIM + (unit & 31) * 4);
                praw[it] = pack_f16x4(v);
            }
            #pragma unroll
            for (int j = 0; j < 2; j++) {          // next self
                int u = j * THREADS + tid;
                int bn = b0n + (u >> 7);
                int bc = (bn < B) ? bn : (B - 1);
                self_s[(buf ^ 1) * (GB * DDIM) + u] = self_v[(size_t)bc * DDIM + (u & 127)];
            }
        }

        // ========== register-resident epilogue (pair-local) ==========
        // thread owns: rows n = mt*16 + 8h + (lane>>2); cols e = nbase + nt*8 + 2(lane&3)+cc
        {
            const float* selfb = self_s + buf * (GB * DDIM) + g * DDIM;

            float s[2][2] = {{0.f, 0.f}, {0.f, 0.f}};
            #pragma unroll
            for (int nt = 0; nt < 8; nt++)
                #pragma unroll
                for (int cc = 0; cc < 2; cc++) {
                    const int e = nbase + nt * 8 + 2 * (lane & 3) + cc;
                    const float sve = selfb[e];
                    const float qve = q_s[e];
                    #pragma unroll
                    for (int mt = 0; mt < 2; mt++)
                        #pragma unroll
                        for (int h = 0; h < 2; h++) {
                            float x = sve * acc[mt][nt][2 * h + cc];
                            x = (x >= 0.f) ? x : LRELU * x;
                            s[mt][h] = fmaf(x, qve, s[mt][h]);
                        }
                }
            #pragma unroll
            for (int mt = 0; mt < 2; mt++)
                #pragma unroll
                for (int h = 0; h < 2; h++) {
                    s[mt][h] += __shfl_xor_sync(0xffffffffu, s[mt][h], 1);
                    s[mt][h] += __shfl_xor_sync(0xffffffffu, s[mt][h], 2);
                }
            if ((lane & 3) == 0) {
                float* pp = part_s + (g * 2 + nw) * 32;
                #pragma unroll
                for (int mt = 0; mt < 2; mt++)
                    #pragma unroll
                    for (int h = 0; h < 2; h++)
                        pp[mt * 16 + 8 * h + (lane >> 2)] = s[mt][h];
            }
            PBAR(g);

            // full score (lane = n), softmax over 32 neighbors
            const float* pg = part_s + g * 2 * 32;
            float sc = pg[lane] + pg[32 + lane];
            float mx = sc;
            #pragma unroll
            for (int o = 16; o; o >>= 1) mx = fmaxf(mx, __shfl_xor_sync(0xffffffffu, mx, o));
            float ex = expf(sc - mx);
            float ssum = ex;
            #pragma unroll
            for (int o = 16; o; o >>= 1) ssum += __shfl_xor_sync(0xffffffffu, ssum, o);
            const float alpha = ex / ssum;

            float ar[2][2];
            #pragma unroll
            for (int mt = 0; mt < 2; mt++)
                #pragma unroll
                for (int h = 0; h < 2; h++)
                    ar[mt][h] = __shfl_sync(0xffffffffu, alpha, mt * 16 + 8 * h + (lane >> 2));
            #pragma unroll
            for (int nt = 0; nt < 8; nt++) {
                float pe0 = 0.f, pe1 = 0.f;
                #pragma unroll
                for (int mt = 0; mt < 2; mt++)
                    #pragma unroll
                    for (int h = 0; h < 2; h++) {
                        pe0 = fmaf(ar[mt][h], acc[mt][nt][2 * h], pe0);
                        pe1 = fmaf(ar[mt][h], acc[mt][nt][2 * h + 1], pe1);
                    }
                #pragma unroll
                for (int o = 4; o <= 16; o <<= 1) {
                    pe0 += __shfl_xor_sync(0xffffffffu, pe0, o);
                    pe1 += __shfl_xor_sync(0xffffffffu, pe1, o);
                }
                if (lane < 4 && b < B)
                    *reinterpret_cast<float2*>(out + (size_t)b * DDIM + nbase + nt * 8 + 2 * lane)
                        = make_float2(pe0, pe1);
            }
        }

        // ---- commit prefetch pass 1 ----
        if (hasnext) {
            #pragma unroll
            for (int it = 0; it < 8; it++) {
                int unit = 4096 + it * THREADS + tid;
                *reinterpret_cast<uint2*>(smem + nb_next
                    + (uint32_t)(unit >> 5) * PITCH_B + (uint32_t)(unit & 31) * 8) = praw[it];
            }
        }
        PBAR(g);    // pair-local: part_s WAR + (pair's share of) commit ordering
        __syncthreads();  // CTA-wide: all pairs' commits visible before next GEMM
        buf ^= 1;
    }
}

extern "C" void kernel_launch(void* const* d_in, const int* in_sizes, int n_in,
                              void* d_out, int out_size) {
    const float* self_v = (const float*)d_in[0];   // [B, 128]
    const float* nb_g   = (const float*)d_in[1];   // [B, 32, 128]
    const float* w_g    = (const float*)d_in[2];   // [128, 128]
    const float* q_g    = (const float*)d_in[3];   // [128, 1]
    float* out = (float*)d_out;

    const int B = in_sizes[0] / DDIM;
    const int ngroups = (B + GB - 1) / GB;

    cudaFuncSetAttribute(hete_agg_hmma8, cudaFuncAttributeMaxDynamicSharedMemorySize, SM_TOTAL);

    int dev = 0, nsm = 148;
    cudaGetDevice(&dev);
    cudaDeviceGetAttribute(&nsm, cudaDevAttrMultiProcessorCount, dev);
    int grid = (ngroups < nsm) ? ngroups : nsm;

    hete_agg_hmma8<<<grid, THREADS, SM_TOTAL>>>(self_v, nb_g, w_g, q_g, out, B);
}

// round 12
// speedup vs baseline: 1.4671x; 1.1133x over previous
#include <cuda_runtime.h>
#include <cuda_fp16.h>
#include <cstdint>

#define THREADS 512
#define DDIM    128
#define NNBR    32
#define GB      8                 // batches per group (one per warp-pair)
#define LRELU   0.2f

#define PITCH_B 272               // bytes/row of fp16 tiles (17*16B -> ldsm conflict-free)

// ---------------- SMEM layout (bytes) ----------------
#define SM_W      0                          // w^T fp16, 128 x 272B = 34816
#define SM_NB0    34816                      // nb fp16 buffer 0: 256 rows x 272B = 69632
#define SM_NB1    104448                     // nb fp16 buffer 1
#define SM_SELF   174080                     // self [2 buf][8][128] fp32 = 8192
#define SM_Q      182272                     // 128 fp32 = 512
#define SM_PART   182784                     // score partials [8 g][2 nw][32] fp32 = 2048
#define SM_TOTAL  184832                     // ~180.5 KB

__device__ __forceinline__ uint32_t smem_u32(const void* p) {
    uint32_t a;
    asm("{ .reg .u64 t; cvta.to.shared.u64 t, %1; cvt.u32.u64 %0, t; }" : "=r"(a) : "l"(p));
    return a;
}
__device__ __forceinline__ void ldsm_x4(uint32_t* r, uint32_t addr) {
    asm volatile("ldmatrix.sync.aligned.m8n8.x4.shared.b16 {%0,%1,%2,%3}, [%4];"
                 : "=r"(r[0]), "=r"(r[1]), "=r"(r[2]), "=r"(r[3]) : "r"(addr));
}
__device__ __forceinline__ void mma16816(float* d, const uint32_t* a, const uint32_t* b) {
    asm volatile("mma.sync.aligned.m16n8k16.row.col.f32.f16.f16.f32 "
                 "{%0,%1,%2,%3}, {%4,%5,%6,%7}, {%8,%9}, {%0,%1,%2,%3};"
                 : "+f"(d[0]), "+f"(d[1]), "+f"(d[2]), "+f"(d[3])
                 : "r"(a[0]), "r"(a[1]), "r"(a[2]), "r"(a[3]), "r"(b[0]), "r"(b[1]));
}
#define PBAR(g) asm volatile("bar.sync %0, 64;" :: "r"((g) + 1) : "memory")

// pack float4 -> 2x fp16x2 via cvt.rn.f16x2.f32
__device__ __forceinline__ uint2 pack_f16x4(float4 v) {
    uint2 r;
    asm("cvt.rn.f16x2.f32 %0, %1, %2;" : "=r"(r.x) : "f"(v.y), "f"(v.x));
    asm("cvt.rn.f16x2.f32 %0, %1, %2;" : "=r"(r.y) : "f"(v.w), "f"(v.z));
    return r;
}

__global__ void __launch_bounds__(THREADS, 1)
hete_agg_hmma9(const float* __restrict__ self_v,
               const float* __restrict__ nb_g,
               const float* __restrict__ w_g,
               const float* __restrict__ q_g,
               float* __restrict__ out,
               int B) {
    extern __shared__ char smem[];
    const uint32_t smb = smem_u32(smem);
    const int tid  = threadIdx.x;
    const int lane = tid & 31;
    const int wid  = tid >> 5;              // 0..15
    const int g    = wid >> 1;              // batch-in-group 0..7 (warp pair)
    const int nw   = wid & 1;               // e-half
    const int ptid = tid & 63;              // thread within pair
    const int mrow0 = g * 32;               // this pair's nb rows
    const int nbase = nw * 64;

    float* self_s = reinterpret_cast<float*>(smem + SM_SELF);
    float* q_s    = reinterpret_cast<float*>(smem + SM_Q);
    float* part_s = reinterpret_cast<float*>(smem + SM_PART);

    // ---- stage w^T fp16 (once); q ----
    for (int idx = tid; idx < DDIM * DDIM; idx += THREADS) {
        int k = idx >> 7, e = idx & 127;
        *reinterpret_cast<__half*>(smem + SM_W + e * PITCH_B + k * 2) =
            __float2half_rn(w_g[idx]);
    }
    if (tid < DDIM) q_s[tid] = q_g[tid];

    const int ngroups = (B + GB - 1) / GB;

    // ---- prologue: each PAIR stages its own batch (buf 0) ----
    int grp = blockIdx.x;
    if (grp < ngroups) {
        const int b = grp * GB + g;
        const int bc = (b < B) ? b : (B - 1);
        #pragma unroll
        for (int it = 0; it < 16; it++) {
            int unit = it * 64 + ptid;          // float4 index within 32x32
            int rl = unit >> 5;                 // local row 0..31
            float4 v = *reinterpret_cast<const float4*>(
                nb_g + ((size_t)bc * NNBR + rl) * DDIM + (unit & 31) * 4);
            *reinterpret_cast<uint2*>(smem + SM_NB0
                + (uint32_t)(mrow0 + rl) * PITCH_B + (uint32_t)(unit & 31) * 8) = pack_f16x4(v);
        }
        #pragma unroll
        for (int j = 0; j < 2; j++) {
            int u = j * 64 + ptid;              // 0..127
            self_s[g * DDIM + u] = self_v[(size_t)bc * DDIM + u];
        }
    }
    __syncthreads();    // one-time CTA-wide: w (and first nb) visible

    int buf = 0;
    for (; grp < ngroups; grp += gridDim.x) {
        const int b = grp * GB + g;
        const int ngrp = grp + gridDim.x;
        const bool hasnext = (ngrp < ngroups);
        int bnc = 0;
        if (hasnext) {
            int bn = ngrp * GB + g;
            bnc = (bn < B) ? bn : (B - 1);
        }
        const uint32_t nb_next = buf ? SM_NB0 : SM_NB1;

        // ---- prefetch pass 0 (local rows 0..15 of next batch) BEFORE GEMM ----
        uint2 praw[8];
        if (hasnext) {
            #pragma unroll
            for (int it = 0; it < 8; it++) {
                int unit = it * 64 + ptid;          // units 0..511 -> rl 0..15
                int rl = unit >> 5;
                float4 v = *reinterpret_cast<const float4*>(
                    nb_g + ((size_t)bnc * NNBR + rl) * DDIM + (unit & 31) * 4);
                praw[it] = pack_f16x4(v);
            }
        }

        // ========== GEMM: acc = nb_f16[g] @ w_f16^T (32 rows x 64 cols) ==========
        float acc[2][8][4];
        #pragma unroll
        for (int mt = 0; mt < 2; mt++)
            #pragma unroll
            for (int nt = 0; nt < 8; nt++)
                #pragma unroll
                for (int j = 0; j < 4; j++) acc[mt][nt][j] = 0.f;

        const uint32_t a_ptr = smb + (buf ? SM_NB1 : SM_NB0)
            + (uint32_t)(mrow0 + (lane & 15)) * PITCH_B + ((lane >> 4) << 4);
        // B pair-load: lanes 0-7 rows n0-7/k0-7; 8-15 n0-7/k8-15; 16-23 n8-15/k0-7; 24-31 n8-15/k8-15
        const uint32_t b_ptr = smb + SM_W
            + (uint32_t)(nbase + ((lane >> 4) << 3) + (lane & 7)) * PITCH_B
            + (((lane >> 3) & 1) << 4);

        #pragma unroll
        for (int ks = 0; ks < 8; ks++) {
            const uint32_t ka = ks * 32;
            uint32_t Ar[2][4];
            ldsm_x4(Ar[0], a_ptr + ka);
            ldsm_x4(Ar[1], a_ptr + 16 * PITCH_B + ka);
            #pragma unroll
            for (int p = 0; p < 4; p++) {          // pair p covers n-tiles 2p,2p+1
                uint32_t Bp[4];
                ldsm_x4(Bp, b_ptr + p * 16 * PITCH_B + ka);
                #pragma unroll
                for (int hf = 0; hf < 2; hf++)
                    #pragma unroll
                    for (int mt = 0; mt < 2; mt++)
                        mma16816(acc[mt][2 * p + hf], Ar[mt], &Bp[2 * hf]);
            }
        }

        // ---- commit pass 0 (data long ready), then issue prefetch pass 1 ----
        if (hasnext) {
            #pragma unroll
            for (int it = 0; it < 8; it++) {
                int unit = it * 64 + ptid;
                *reinterpret_cast<uint2*>(smem + nb_next
                    + (uint32_t)(mrow0 + (unit >> 5)) * PITCH_B
                    + (uint32_t)(unit & 31) * 8) = praw[it];
            }
            #pragma unroll
            for (int it = 0; it < 8; it++) {       // units 512..1023 -> rl 16..31
                int unit = 512 + it * 64 + ptid;
                int rl = unit >> 5;
                float4 v = *reinterpret_cast<const float4*>(
                    nb_g + ((size_t)bnc * NNBR + rl) * DDIM + (unit & 31) * 4);
                praw[it] = pack_f16x4(v);
            }
            #pragma unroll
            for (int j = 0; j < 2; j++) {          // next self (pair-local slice)
                int u = j * 64 + ptid;
                self_s[(buf ^ 1) * (GB * DDIM) + g * DDIM + u] =
                    self_v[(size_t)bnc * DDIM + u];
            }
        }

        // ========== register-resident epilogue (pair-local) ==========
        // thread owns: rows n = mt*16 + 8h + (lane>>2); cols e = nbase + nt*8 + 2(lane&3)+cc
        {
            const float* selfb = self_s + buf * (GB * DDIM) + g * DDIM;

            float s[2][2] = {{0.f, 0.f}, {0.f, 0.f}};
            #pragma unroll
            for (int nt = 0; nt < 8; nt++)
                #pragma unroll
                for (int cc = 0; cc < 2; cc++) {
                    const int e = nbase + nt * 8 + 2 * (lane & 3) + cc;
                    const float sve = selfb[e];
                    const float qve = q_s[e];
                    #pragma unroll
                    for (int mt = 0; mt < 2; mt++)
                        #pragma unroll
                        for (int h = 0; h < 2; h++) {
                            float x = sve * acc[mt][nt][2 * h + cc];
                            x = (x >= 0.f) ? x : LRELU * x;
                            s[mt][h] = fmaf(x, qve, s[mt][h]);
                        }
                }
            #pragma unroll
            for (int mt = 0; mt < 2; mt++)
                #pragma unroll
                for (int h = 0; h < 2; h++) {
                    s[mt][h] += __shfl_xor_sync(0xffffffffu, s[mt][h], 1);
                    s[mt][h] += __shfl_xor_sync(0xffffffffu, s[mt][h], 2);
                }
            if ((lane & 3) == 0) {
                float* pp = part_s + (g * 2 + nw) * 32;
                #pragma unroll
                for (int mt = 0; mt < 2; mt++)
                    #pragma unroll
                    for (int h = 0; h < 2; h++)
                        pp[mt * 16 + 8 * h + (lane >> 2)] = s[mt][h];
            }
            PBAR(g);

            // full score (lane = n), softmax over 32 neighbors
            const float* pg = part_s + g * 2 * 32;
            float sc = pg[lane] + pg[32 + lane];
            float mx = sc;
            #pragma unroll
            for (int o = 16; o; o >>= 1) mx = fmaxf(mx, __shfl_xor_sync(0xffffffffu, mx, o));
            float ex = __expf(sc - mx);
            float ssum = ex;
            #pragma unroll
            for (int o = 16; o; o >>= 1) ssum += __shfl_xor_sync(0xffffffffu, ssum, o);
            const float alpha = ex / ssum;

            float ar[2][2];
            #pragma unroll
            for (int mt = 0; mt < 2; mt++)
                #pragma unroll
                for (int h = 0; h < 2; h++)
                    ar[mt][h] = __shfl_sync(0xffffffffu, alpha, mt * 16 + 8 * h + (lane >> 2));
            #pragma unroll
            for (int nt = 0; nt < 8; nt++) {
                float pe0 = 0.f, pe1 = 0.f;
                #pragma unroll
                for (int mt = 0; mt < 2; mt++)
                    #pragma unroll
                    for (int h = 0; h < 2; h++) {
                        pe0 = fmaf(ar[mt][h], acc[mt][nt][2 * h], pe0);
                        pe1 = fmaf(ar[mt][h], acc[mt][nt][2 * h + 1], pe1);
                    }
                #pragma unroll
                for (int o = 4; o <= 16; o <<= 1) {
                    pe0 += __shfl_xor_sync(0xffffffffu, pe0, o);
                    pe1 += __shfl_xor_sync(0xffffffffu, pe1, o);
                }
                if (lane < 4 && b < B)
                    *reinterpret_cast<float2*>(out + (size_t)b * DDIM + nbase + nt * 8 + 2 * lane)
                        = make_float2(pe0, pe1);
            }
        }

        // ---- commit prefetch pass 1 ----
        if (hasnext) {
            #pragma unroll
            for (int it = 0; it < 8; it++) {
                int unit = 512 + it * 64 + ptid;
                *reinterpret_cast<uint2*>(smem + nb_next
                    + (uint32_t)(mrow0 + (unit >> 5)) * PITCH_B
                    + (uint32_t)(unit & 31) * 8) = praw[it];
            }
        }
        PBAR(g);    // pair-local only: commit visibility + part_s/self WAR ordering
        buf ^= 1;
    }
}

extern "C" void kernel_launch(void* const* d_in, const int* in_sizes, int n_in,
                              void* d_out, int out_size) {
    const float* self_v = (const float*)d_in[0];   // [B, 128]
    const float* nb_g   = (const float*)d_in[1];   // [B, 32, 128]
    const float* w_g    = (const float*)d_in[2];   // [128, 128]
    const float* q_g    = (const float*)d_in[3];   // [128, 1]
    float* out = (float*)d_out;

    const int B = in_sizes[0] / DDIM;
    const int ngroups = (B + GB - 1) / GB;

    cudaFuncSetAttribute(hete_agg_hmma9, cudaFuncAttributeMaxDynamicSharedMemorySize, SM_TOTAL);

    int dev = 0, nsm = 148;
    cudaGetDevice(&dev);
    cudaDeviceGetAttribute(&nsm, cudaDevAttrMultiProcessorCount, dev);
    int grid = (ngroups < nsm) ? ngroups : nsm;

    hete_agg_hmma9<<<grid, THREADS, SM_TOTAL>>>(self_v, nb_g, w_g, q_g, out, B);
}